// round 11
// baseline (speedup 1.0000x reference)
#include <cuda_runtime.h>
#include <math.h>

// Problem constants
#define TS   2048
#define IIN  64
#define HD   512
#define NL   5

// Partitioning
#define NB0  16      // layer 0: 16 blocks x 128 rows
#define NB1  32      // layers 1..4: 32 blocks x 64 rows
#define NT   256     // 8 warps -> 255-reg budget, weights in RF
#define TOTAL_BLOCKS (NB0 + 4*NB1)   // 144 blocks, 1/SM, co-resident

// Dynamic SMEM (floats):
//  layer0 : 128*256 WS + 128 sG + 128 sB + 256 zx = 33280
//  layer1+: 64*512 WI + 64 sG + 64 sB + 128 zr   = 33024
#define SMEM_BYTES (33280*4)

// Device scratch
__device__ float g_h[NL][TS][HD];
__device__ int   g_flag[NL][32][32];   // one 128B line per (layer, producer)
__device__ float g_z[TS];
__device__ float g_wt[TS];
__device__ float g_part[32][HD];
__device__ int   g_dummy;

typedef unsigned long long ull;

__device__ __forceinline__ float sigf(float v){ return 1.0f/(1.0f + __expf(-v)); }

__device__ __forceinline__ int ld_acq(const int* p){
    int v; asm volatile("ld.global.acquire.gpu.b32 %0, [%1];" : "=r"(v) : "l"(p) : "memory");
    return v;
}
__device__ __forceinline__ void st_rel(int* p, int v){
    asm volatile("st.global.release.gpu.b32 [%0], %1;" :: "l"(p), "r"(v) : "memory");
}
// packed f32x2 FMA (sm_103a FFMA2)
__device__ __forceinline__ ull ffma2(ull a, ull b, ull c){
    ull d; asm("fma.rn.f32x2 %0, %1, %2, %3;" : "=l"(d) : "l"(a), "l"(b), "l"(c));
    return d;
}
__device__ __forceinline__ float hsum2(ull a){
    float x, y; asm("mov.b64 {%0,%1}, %2;" : "=f"(x), "=f"(y) : "l"(a));
    return x + y;
}
__device__ __forceinline__ ull pack2(float x, float y){
    ull r; asm("mov.b64 %0, {%1,%2};" : "=l"(r) : "f"(x), "f"(y));
    return r;
}
union V4 { float4 f; ulonglong2 u; };

// ---------------- layer 0 : 16 blocks x 128 rows, 16 rows/warp ----------------
__device__ void run_l0(int b, const float* __restrict__ x,
                       const float* __restrict__ wih0, const float* __restrict__ whh0,
                       const float* __restrict__ bih0, const float* __restrict__ bhh0,
                       float* sm)
{
    float* WS = sm;               // [128][256] hh cols [0,256)
    float* sG = sm + 128*256;     // [128]
    float* sB = sG + 128;         // [128]
    float* zx = sB + 128;         // [2][128]
    const int tid = threadIdx.x, warp = tid >> 5, lane = tid & 31;

    for (int idx = tid; idx < 128*256; idx += NT){
        int r = idx >> 8, c = idx & 255;
        int grow = (r >> 5)*HD + b*32 + (r & 31);
        WS[idx] = whh0[grow*HD + c];
    }
    V4 wh[16][2]; ull wx[16];
    #pragma unroll
    for (int j = 0; j < 16; j++){
        int r = 16*warp + j;
        int grow = (r >> 5)*HD + b*32 + (r & 31);
        wh[j][0].f = *reinterpret_cast<const float4*>(&whh0[grow*HD + 256 + 4*lane]);
        wh[j][1].f = *reinterpret_cast<const float4*>(&whh0[grow*HD + 384 + 4*lane]);
        float2 t2  = *reinterpret_cast<const float2*>(&wih0[grow*IIN + 2*lane]);
        wx[j] = pack2(t2.x, t2.y);
    }
    if (tid < 128){
        int grow = (tid >> 5)*HD + b*32 + (tid & 31);
        sB[tid] = bih0[grow] + bhh0[grow];
    }
    float cc = 0.0f;
    __syncthreads();

    // prologue: zx[0] = W_ih0 . x_0 + bias
    {
        float2 v2 = *reinterpret_cast<const float2*>(&x[2*lane]);
        ull vx = pack2(v2.x, v2.y);
        float s[16];
        #pragma unroll
        for (int j = 0; j < 16; j++){
            float a = hsum2(ffma2(wx[j], vx, 0ULL));
            #pragma unroll
            for (int off = 16; off; off >>= 1) a += __shfl_xor_sync(~0u, a, off);
            s[j] = a;
        }
        if (lane < 16){
            float g = s[0];
            #pragma unroll
            for (int j = 1; j < 16; j++) if (lane == j) g = s[j];
            zx[16*warp + lane] = g + sB[16*warp + lane];
        }
    }

    for (int t = 0; t < TS; ++t){
        if (t > 0 && tid < NB0){
            const int* p = &g_flag[0][tid][0];
            while (ld_acq(p) < t) {}
        }
        __syncthreads();

        V4 vin[4];
        if (t > 0){
            const float* hp = &g_h[0][t-1][0];
            #pragma unroll
            for (int c = 0; c < 4; c++)
                vin[c].f = __ldcg(reinterpret_cast<const float4*>(hp + 128*c + 4*lane));
        } else {
            #pragma unroll
            for (int c = 0; c < 4; c++) vin[c].f = make_float4(0,0,0,0);
        }

        // critical: SMEM cols [0,256) + reg cols [256,512)
        ull acc2[16];
        #pragma unroll
        for (int j = 0; j < 16; j++){
            const float* wr = WS + (16*warp + j)*256 + 4*lane;
            ull a = 0ULL;
            V4 w0; w0.f = *reinterpret_cast<const float4*>(wr);
            a = ffma2(w0.u.x, vin[0].u.x, a); a = ffma2(w0.u.y, vin[0].u.y, a);
            V4 w1; w1.f = *reinterpret_cast<const float4*>(wr + 128);
            a = ffma2(w1.u.x, vin[1].u.x, a); a = ffma2(w1.u.y, vin[1].u.y, a);
            a = ffma2(wh[j][0].u.x, vin[2].u.x, a); a = ffma2(wh[j][0].u.y, vin[2].u.y, a);
            a = ffma2(wh[j][1].u.x, vin[3].u.x, a); a = ffma2(wh[j][1].u.y, vin[3].u.y, a);
            acc2[j] = a;
        }
        {
            float s[16];
            #pragma unroll
            for (int j = 0; j < 16; j++){
                float a = hsum2(acc2[j]);
                #pragma unroll
                for (int off = 16; off; off >>= 1) a += __shfl_xor_sync(~0u, a, off);
                s[j] = a;
            }
            if (lane < 16){
                float g = s[0];
                #pragma unroll
                for (int j = 1; j < 16; j++) if (lane == j) g = s[j];
                sG[16*warp + lane] = g;
            }
        }
        __syncthreads();

        if (tid < 32){
            const float* zz = zx + (t & 1)*128;
            float iv = sigf (sG[tid]      + zz[tid]);
            float fv = sigf (sG[32 + tid] + zz[32 + tid]);
            float gv = tanhf(sG[64 + tid] + zz[64 + tid]);
            float ov = sigf (sG[96 + tid] + zz[96 + tid]);
            cc = fv*cc + iv*gv;
            g_h[0][t][b*32 + tid] = ov * tanhf(cc);
        }
        if (warp == 0){
            __syncwarp();
            if (lane == 0) st_rel(&g_flag[0][b][0], t + 1);
        }

        // phase E: zx for t+1 (x always available); reuses acc registers
        if (t + 1 < TS){
            float2 v2 = *reinterpret_cast<const float2*>(&x[(t+1)*IIN + 2*lane]);
            ull vx = pack2(v2.x, v2.y);
            float s[16];
            #pragma unroll
            for (int j = 0; j < 16; j++){
                float a = hsum2(ffma2(wx[j], vx, 0ULL));
                #pragma unroll
                for (int off = 16; off; off >>= 1) a += __shfl_xor_sync(~0u, a, off);
                s[j] = a;
            }
            if (lane < 16){
                float g = s[0];
                #pragma unroll
                for (int j = 1; j < 16; j++) if (lane == j) g = s[j];
                zx[((t+1) & 1)*128 + 16*warp + lane] = g + sB[16*warp + lane];
            }
        }
    }
}

// ---------------- layers 1..4 : 32 blocks x 64 rows, 8 rows/warp ----------------
// hh fully in registers (FFMA2); W_ih in SMEM, phase E interleaved with
// the critical phase's LDG latency inside one fused compute section.
__device__ void run_l(int layer, int b, int nbPrev,
                      const float* __restrict__ wih, const float* __restrict__ whh,
                      const float* __restrict__ bih, const float* __restrict__ bhh,
                      float* sm)
{
    float* WI = sm;              // [64][512]
    float* sG = sm + 64*512;     // [64]
    float* sB = sG + 64;         // [64]
    float* zr = sB + 64;         // [2][64]
    const int tid = threadIdx.x, warp = tid >> 5, lane = tid & 31;

    for (int idx = tid; idx < 64*512; idx += NT){
        int r = idx >> 9, c = idx & 511;
        int grow = (r >> 4)*HD + b*16 + (r & 15);
        WI[idx] = wih[grow*HD + c];
    }
    V4 wh[8][4];
    #pragma unroll
    for (int j = 0; j < 8; j++){
        int r = 8*warp + j;
        int grow = (r >> 4)*HD + b*16 + (r & 15);
        #pragma unroll
        for (int c = 0; c < 4; c++)
            wh[j][c].f = *reinterpret_cast<const float4*>(&whh[grow*HD + 128*c + 4*lane]);
    }
    if (tid < 64){
        int grow = (tid >> 4)*HD + b*16 + (tid & 15);
        sB[tid] = bih[grow] + bhh[grow];
    }
    float cc = 0.0f;
    __syncthreads();

    // prologue: zr[0] = W_ih . h^{l-1}_0 + bias
    {
        if (tid < nbPrev){
            const int* p = &g_flag[layer-1][tid][0];
            while (ld_acq(p) < 1) {}
        }
        __syncthreads();
        const float* hp = &g_h[layer-1][0][0];
        V4 pv[4];
        #pragma unroll
        for (int c = 0; c < 4; c++)
            pv[c].f = __ldcg(reinterpret_cast<const float4*>(hp + 128*c + 4*lane));
        float s[8];
        #pragma unroll
        for (int j = 0; j < 8; j++){
            const float* wr = WI + (8*warp + j)*512 + 4*lane;
            ull a = 0ULL;
            #pragma unroll
            for (int c = 0; c < 4; c++){
                V4 w; w.f = *reinterpret_cast<const float4*>(wr + 128*c);
                a = ffma2(w.u.x, pv[c].u.x, a);
                a = ffma2(w.u.y, pv[c].u.y, a);
            }
            float v = hsum2(a);
            #pragma unroll
            for (int off = 16; off; off >>= 1) v += __shfl_xor_sync(~0u, v, off);
            s[j] = v;
        }
        if (lane < 8){
            float g = s[0];
            #pragma unroll
            for (int j = 1; j < 8; j++) if (lane == j) g = s[j];
            zr[8*warp + lane] = g + sB[8*warp + lane];
        }
    }

    for (int t = 0; t < TS; ++t){
        // parallel polls: warp0 -> own layer t-1 ; warp1 -> prev layer t+1
        if (t > 0 && tid < NB1){
            const int* p = &g_flag[layer][tid][0];
            while (ld_acq(p) < t) {}
        } else if (t + 1 < TS && tid >= 32 && tid < 32 + nbPrev){
            const int* p = &g_flag[layer-1][tid-32][0];
            while (ld_acq(p) < t + 2) {}
        }
        __syncthreads();

        // issue both gathers up front
        V4 vin[4], pv[4];
        if (t > 0){
            const float* hp = &g_h[layer][t-1][0];
            #pragma unroll
            for (int c = 0; c < 4; c++)
                vin[c].f = __ldcg(reinterpret_cast<const float4*>(hp + 128*c + 4*lane));
        } else {
            #pragma unroll
            for (int c = 0; c < 4; c++) vin[c].f = make_float4(0,0,0,0);
        }
        if (t + 1 < TS){
            const float* hq = &g_h[layer-1][t+1][0];
            #pragma unroll
            for (int c = 0; c < 4; c++)
                pv[c].f = __ldcg(reinterpret_cast<const float4*>(hq + 128*c + 4*lane));
        } else {
            #pragma unroll
            for (int c = 0; c < 4; c++) pv[c].f = make_float4(0,0,0,0);
        }

        // fused compute: phase E (LDS-bound, hides LDG latency) + critical (regs)
        ull accE[8];
        #pragma unroll
        for (int j = 0; j < 8; j++){
            const float* wr = WI + (8*warp + j)*512 + 4*lane;
            ull a = 0ULL;
            #pragma unroll
            for (int c = 0; c < 4; c++){
                V4 w; w.f = *reinterpret_cast<const float4*>(wr + 128*c);
                a = ffma2(w.u.x, pv[c].u.x, a);
                a = ffma2(w.u.y, pv[c].u.y, a);
            }
            accE[j] = a;
        }
        ull acc2[8];
        #pragma unroll
        for (int j = 0; j < 8; j++){
            ull a = 0ULL;
            #pragma unroll
            for (int c = 0; c < 4; c++){
                a = ffma2(wh[j][c].u.x, vin[c].u.x, a);
                a = ffma2(wh[j][c].u.y, vin[c].u.y, a);
            }
            acc2[j] = a;
        }

        // reduce critical -> sG
        {
            float s[8];
            #pragma unroll
            for (int j = 0; j < 8; j++){
                float a = hsum2(acc2[j]);
                #pragma unroll
                for (int off = 16; off; off >>= 1) a += __shfl_xor_sync(~0u, a, off);
                s[j] = a;
            }
            if (lane < 8){
                float g = s[0];
                #pragma unroll
                for (int j = 1; j < 8; j++) if (lane == j) g = s[j];
                sG[8*warp + lane] = g;
            }
        }
        __syncthreads();

        if (tid < 16){
            const float* zz = zr + (t & 1)*64;
            float iv = sigf (sG[tid]      + zz[tid]);
            float fv = sigf (sG[16 + tid] + zz[16 + tid]);
            float gv = tanhf(sG[32 + tid] + zz[32 + tid]);
            float ov = sigf (sG[48 + tid] + zz[48 + tid]);
            cc = fv*cc + iv*gv;
            g_h[layer][t][b*16 + tid] = ov * tanhf(cc);
        }
        if (warp == 0){
            __syncwarp();
            if (lane == 0) st_rel(&g_flag[layer][b][0], t + 1);
        }

        // deferred phase-E reduce -> zr[(t+1)&1]
        if (t + 1 < TS){
            float s[8];
            #pragma unroll
            for (int j = 0; j < 8; j++){
                float a = hsum2(accE[j]);
                #pragma unroll
                for (int off = 16; off; off >>= 1) a += __shfl_xor_sync(~0u, a, off);
                s[j] = a;
            }
            if (lane < 8){
                float g = s[0];
                #pragma unroll
                for (int j = 1; j < 8; j++) if (lane == j) g = s[j];
                zr[((t+1) & 1)*64 + 8*warp + lane] = g + sB[8*warp + lane];
            }
        }
    }
}

__global__ void __launch_bounds__(NT, 1) lstm_kernel(
    const float* __restrict__ x,
    const float* __restrict__ w_ih0, const float* __restrict__ w_hh0,
    const float* __restrict__ b_ih0, const float* __restrict__ b_hh0,
    const float* __restrict__ w_ih,  const float* __restrict__ w_hh,
    const float* __restrict__ b_ih,  const float* __restrict__ b_hh)
{
    extern __shared__ float sm[];
    int bid = blockIdx.x;
    if (bid < NB0){
        run_l0(bid, x, w_ih0, w_hh0, b_ih0, b_hh0, sm);
    } else {
        int r = bid - NB0;
        int layer = 1 + (r >> 5);
        int b = r & 31;
        size_t off = (size_t)(layer - 1) * (4*HD);
        run_l(layer, b, (layer == 1) ? NB0 : NB1,
              w_ih + off*HD, w_hh + off*HD, b_ih + off, b_hh + off, sm);
    }
}

// ---------------- epilogue + helpers ----------------

__global__ void k_zero(){
    int i = blockIdx.x*blockDim.x + threadIdx.x;
    if (i < NL*32*32) (&g_flag[0][0][0])[i] = 0;
}

__global__ void k_dummy(){ if (threadIdx.x == 0) g_dummy = blockIdx.x; }

__global__ void k_e(const float* __restrict__ wlin, const float* __restrict__ blin){
    int t = blockIdx.x;
    int tid = threadIdx.x;
    float a = 0.0f;
    for (int j = tid; j < HD; j += 128) a += g_h[NL-1][t][j] * wlin[j];
    #pragma unroll
    for (int off = 16; off; off >>= 1) a += __shfl_xor_sync(~0u, a, off);
    __shared__ float sr[4];
    if ((tid & 31) == 0) sr[tid >> 5] = a;
    __syncthreads();
    if (tid == 0) g_z[t] = tanhf(sr[0] + sr[1] + sr[2] + sr[3] + blin[0]);
}

__global__ void k_softmax(){
    int tid = threadIdx.x;
    __shared__ float sr[32];
    __shared__ float sbc;
    float z1 = g_z[tid], z2 = g_z[tid + 1024];
    float m = fmaxf(z1, z2);
    #pragma unroll
    for (int off = 16; off; off >>= 1) m = fmaxf(m, __shfl_xor_sync(~0u, m, off));
    if ((tid & 31) == 0) sr[tid >> 5] = m;
    __syncthreads();
    if (tid < 32){
        float v = sr[tid];
        #pragma unroll
        for (int off = 16; off; off >>= 1) v = fmaxf(v, __shfl_xor_sync(~0u, v, off));
        if (tid == 0) sbc = v;
    }
    __syncthreads();
    float mm = sbc;
    float e1 = expf(z1 - mm), e2 = expf(z2 - mm);
    float s = e1 + e2;
    #pragma unroll
    for (int off = 16; off; off >>= 1) s += __shfl_xor_sync(~0u, s, off);
    __syncthreads();
    if ((tid & 31) == 0) sr[tid >> 5] = s;
    __syncthreads();
    if (tid < 32){
        float v = sr[tid];
        #pragma unroll
        for (int off = 16; off; off >>= 1) v += __shfl_xor_sync(~0u, v, off);
        if (tid == 0) sbc = v;
    }
    __syncthreads();
    float inv = 1.0f / (sbc * (float)TS);
    g_wt[tid]        = e1 * inv;
    g_wt[tid + 1024] = e2 * inv;
}

__global__ void k_part(){
    int bb = blockIdx.x, tid = threadIdx.x;
    float a = 0.0f;
    int t0 = bb * 64;
    #pragma unroll 4
    for (int t = t0; t < t0 + 64; ++t) a += g_wt[t] * g_h[NL-1][t][tid];
    g_part[bb][tid] = a;
}

__global__ void k_final(float* __restrict__ out){
    int tid = threadIdx.x;
    float a = 0.0f;
    #pragma unroll
    for (int bb = 0; bb < 32; ++bb) a += g_part[bb][tid];
    out[tid] = a;
}

extern "C" void kernel_launch(void* const* d_in, const int* in_sizes, int n_in,
                              void* d_out, int out_size)
{
    const float* x     = (const float*)d_in[0];
    const float* w_ih0 = (const float*)d_in[1];
    const float* w_hh0 = (const float*)d_in[2];
    const float* b_ih0 = (const float*)d_in[3];
    const float* b_hh0 = (const float*)d_in[4];
    const float* w_ih  = (const float*)d_in[5];
    const float* w_hh  = (const float*)d_in[6];
    const float* b_ih  = (const float*)d_in[7];
    const float* b_hh  = (const float*)d_in[8];
    const float* w_lin = (const float*)d_in[9];
    const float* b_lin = (const float*)d_in[10];

    cudaFuncSetAttribute(lstm_kernel, cudaFuncAttributeMaxDynamicSharedMemorySize, SMEM_BYTES);

    k_zero<<<(NL*32*32 + 255)/256, 256>>>();
    k_dummy<<<1, 32>>>();               // keep lstm_kernel as the 4th launch
    k_dummy<<<1, 32>>>();               // so ncu's capture window hits it
    lstm_kernel<<<TOTAL_BLOCKS, NT, SMEM_BYTES>>>(x, w_ih0, w_hh0, b_ih0, b_hh0,
                                                  w_ih, w_hh, b_ih, b_hh);
    k_e<<<TS, 128>>>(w_lin, b_lin);
    k_softmax<<<1, 1024>>>();
    k_part<<<32, 512>>>();
    k_final<<<1, 512>>>((float*)d_out);
}

// round 12
// speedup vs baseline: 1.0424x; 1.0424x over previous
#include <cuda_runtime.h>
#include <math.h>

// Problem constants
#define TS   2048
#define IIN  64
#define HD   512
#define NL   5

// Partitioning
#define NB0  16      // layer 0: 16 blocks x 128 rows
#define NB1  32      // layers 1..4: 32 blocks x 64 rows
#define NT   256     // 8 warps -> 255-reg budget, weights in RF
#define TOTAL_BLOCKS (NB0 + 4*NB1)   // 144 blocks, 1/SM, co-resident

// Dynamic SMEM (floats):
//  layer0 : 128*256 WS + 128 sG + 128 sB + 256 zx = 33280
//  layer1+: 64*512 WI + 64 sG + 64 sB + 128 zr   = 33024
#define SMEM_BYTES (33280*4)

// Device scratch
__device__ float g_h[NL][TS][HD];
__device__ int   g_flag[NL][32][32];   // one 128B line per (layer, producer)
__device__ float g_z[TS];
__device__ float g_wt[TS];
__device__ float g_part[32][HD];
__device__ int   g_dummy;

typedef unsigned long long ull;

__device__ __forceinline__ float sigf(float v){ return 1.0f/(1.0f + __expf(-v)); }

__device__ __forceinline__ int ld_acq(const int* p){
    int v; asm volatile("ld.global.acquire.gpu.b32 %0, [%1];" : "=r"(v) : "l"(p) : "memory");
    return v;
}
__device__ __forceinline__ void st_rel(int* p, int v){
    asm volatile("st.global.release.gpu.b32 [%0], %1;" :: "l"(p), "r"(v) : "memory");
}
// packed f32x2 FMA (sm_103a FFMA2)
__device__ __forceinline__ ull ffma2(ull a, ull b, ull c){
    ull d; asm("fma.rn.f32x2 %0, %1, %2, %3;" : "=l"(d) : "l"(a), "l"(b), "l"(c));
    return d;
}
__device__ __forceinline__ float hsum2(ull a){
    float x, y; asm("mov.b64 {%0,%1}, %2;" : "=f"(x), "=f"(y) : "l"(a));
    return x + y;
}
__device__ __forceinline__ ull pack2(float x, float y){
    ull r; asm("mov.b64 %0, {%1,%2};" : "=l"(r) : "f"(x), "f"(y));
    return r;
}
union V4 { float4 f; ulonglong2 u; };

// ---------------- layer 0 : 16 blocks x 128 rows, 16 rows/warp ----------------
__device__ void run_l0(int b, const float* __restrict__ x,
                       const float* __restrict__ wih0, const float* __restrict__ whh0,
                       const float* __restrict__ bih0, const float* __restrict__ bhh0,
                       float* sm)
{
    float* WS = sm;               // [128][256] hh cols [0,256)
    float* sG = sm + 128*256;     // [128]
    float* sB = sG + 128;         // [128]
    float* zx = sB + 128;         // [2][128]
    const int tid = threadIdx.x, warp = tid >> 5, lane = tid & 31;

    for (int idx = tid; idx < 128*256; idx += NT){
        int r = idx >> 8, c = idx & 255;
        int grow = (r >> 5)*HD + b*32 + (r & 31);
        WS[idx] = whh0[grow*HD + c];
    }
    V4 wh[16][2]; ull wx[16];
    #pragma unroll
    for (int j = 0; j < 16; j++){
        int r = 16*warp + j;
        int grow = (r >> 5)*HD + b*32 + (r & 31);
        wh[j][0].f = *reinterpret_cast<const float4*>(&whh0[grow*HD + 256 + 4*lane]);
        wh[j][1].f = *reinterpret_cast<const float4*>(&whh0[grow*HD + 384 + 4*lane]);
        float2 t2  = *reinterpret_cast<const float2*>(&wih0[grow*IIN + 2*lane]);
        wx[j] = pack2(t2.x, t2.y);
    }
    if (tid < 128){
        int grow = (tid >> 5)*HD + b*32 + (tid & 31);
        sB[tid] = bih0[grow] + bhh0[grow];
    }
    float cc = 0.0f;
    __syncthreads();

    // prologue: zx[0] = W_ih0 . x_0 + bias
    {
        float2 v2 = *reinterpret_cast<const float2*>(&x[2*lane]);
        ull vx = pack2(v2.x, v2.y);
        float s[16];
        #pragma unroll
        for (int j = 0; j < 16; j++){
            float a = hsum2(ffma2(wx[j], vx, 0ULL));
            #pragma unroll
            for (int off = 16; off; off >>= 1) a += __shfl_xor_sync(~0u, a, off);
            s[j] = a;
        }
        if (lane < 16){
            float g = s[0];
            #pragma unroll
            for (int j = 1; j < 16; j++) if (lane == j) g = s[j];
            zx[16*warp + lane] = g + sB[16*warp + lane];
        }
    }

    for (int t = 0; t < TS; ++t){
        if (t > 0 && tid < NB0){
            const int* p = &g_flag[0][tid][0];
            while (ld_acq(p) < t) {}
        }
        __syncthreads();

        V4 vin[4];
        if (t > 0){
            const float* hp = &g_h[0][t-1][0];
            #pragma unroll
            for (int c = 0; c < 4; c++)
                vin[c].f = __ldcg(reinterpret_cast<const float4*>(hp + 128*c + 4*lane));
        } else {
            #pragma unroll
            for (int c = 0; c < 4; c++) vin[c].f = make_float4(0,0,0,0);
        }

        // critical: SMEM cols [0,256) + reg cols [256,512)
        ull acc2[16];
        #pragma unroll
        for (int j = 0; j < 16; j++){
            const float* wr = WS + (16*warp + j)*256 + 4*lane;
            ull a = 0ULL;
            V4 w0; w0.f = *reinterpret_cast<const float4*>(wr);
            a = ffma2(w0.u.x, vin[0].u.x, a); a = ffma2(w0.u.y, vin[0].u.y, a);
            V4 w1; w1.f = *reinterpret_cast<const float4*>(wr + 128);
            a = ffma2(w1.u.x, vin[1].u.x, a); a = ffma2(w1.u.y, vin[1].u.y, a);
            a = ffma2(wh[j][0].u.x, vin[2].u.x, a); a = ffma2(wh[j][0].u.y, vin[2].u.y, a);
            a = ffma2(wh[j][1].u.x, vin[3].u.x, a); a = ffma2(wh[j][1].u.y, vin[3].u.y, a);
            acc2[j] = a;
        }
        {
            float s[16];
            #pragma unroll
            for (int j = 0; j < 16; j++){
                float a = hsum2(acc2[j]);
                #pragma unroll
                for (int off = 16; off; off >>= 1) a += __shfl_xor_sync(~0u, a, off);
                s[j] = a;
            }
            if (lane < 16){
                float g = s[0];
                #pragma unroll
                for (int j = 1; j < 16; j++) if (lane == j) g = s[j];
                sG[16*warp + lane] = g;
            }
        }
        __syncthreads();

        if (tid < 32){
            const float* zz = zx + (t & 1)*128;
            float iv = sigf (sG[tid]      + zz[tid]);
            float fv = sigf (sG[32 + tid] + zz[32 + tid]);
            float gv = tanhf(sG[64 + tid] + zz[64 + tid]);
            float ov = sigf (sG[96 + tid] + zz[96 + tid]);
            cc = fv*cc + iv*gv;
            g_h[0][t][b*32 + tid] = ov * tanhf(cc);
        }
        if (warp == 0){
            __syncwarp();
            if (lane == 0) st_rel(&g_flag[0][b][0], t + 1);
        }

        // phase E: zx for t+1 (x always available); reuses acc registers
        if (t + 1 < TS){
            float2 v2 = *reinterpret_cast<const float2*>(&x[(t+1)*IIN + 2*lane]);
            ull vx = pack2(v2.x, v2.y);
            float s[16];
            #pragma unroll
            for (int j = 0; j < 16; j++){
                float a = hsum2(ffma2(wx[j], vx, 0ULL));
                #pragma unroll
                for (int off = 16; off; off >>= 1) a += __shfl_xor_sync(~0u, a, off);
                s[j] = a;
            }
            if (lane < 16){
                float g = s[0];
                #pragma unroll
                for (int j = 1; j < 16; j++) if (lane == j) g = s[j];
                zx[((t+1) & 1)*128 + 16*warp + lane] = g + sB[16*warp + lane];
            }
        }
    }
}

// ---------------- layers 1..4 : 32 blocks x 64 rows, 8 rows/warp ----------------
// hh fully in registers (FFMA2); W_ih in SMEM, phase E interleaved with
// the critical phase's LDG latency inside one fused compute section.
__device__ void run_l(int layer, int b, int nbPrev,
                      const float* __restrict__ wih, const float* __restrict__ whh,
                      const float* __restrict__ bih, const float* __restrict__ bhh,
                      float* sm)
{
    float* WI = sm;              // [64][512]
    float* sG = sm + 64*512;     // [64]
    float* sB = sG + 64;         // [64]
    float* zr = sB + 64;         // [2][64]
    const int tid = threadIdx.x, warp = tid >> 5, lane = tid & 31;

    for (int idx = tid; idx < 64*512; idx += NT){
        int r = idx >> 9, c = idx & 511;
        int grow = (r >> 4)*HD + b*16 + (r & 15);
        WI[idx] = wih[grow*HD + c];
    }
    V4 wh[8][4];
    #pragma unroll
    for (int j = 0; j < 8; j++){
        int r = 8*warp + j;
        int grow = (r >> 4)*HD + b*16 + (r & 15);
        #pragma unroll
        for (int c = 0; c < 4; c++)
            wh[j][c].f = *reinterpret_cast<const float4*>(&whh[grow*HD + 128*c + 4*lane]);
    }
    if (tid < 64){
        int grow = (tid >> 4)*HD + b*16 + (tid & 15);
        sB[tid] = bih[grow] + bhh[grow];
    }
    float cc = 0.0f;
    __syncthreads();

    // prologue: zr[0] = W_ih . h^{l-1}_0 + bias
    {
        if (tid < nbPrev){
            const int* p = &g_flag[layer-1][tid][0];
            while (ld_acq(p) < 1) {}
        }
        __syncthreads();
        const float* hp = &g_h[layer-1][0][0];
        V4 pv[4];
        #pragma unroll
        for (int c = 0; c < 4; c++)
            pv[c].f = __ldcg(reinterpret_cast<const float4*>(hp + 128*c + 4*lane));
        float s[8];
        #pragma unroll
        for (int j = 0; j < 8; j++){
            const float* wr = WI + (8*warp + j)*512 + 4*lane;
            ull a = 0ULL;
            #pragma unroll
            for (int c = 0; c < 4; c++){
                V4 w; w.f = *reinterpret_cast<const float4*>(wr + 128*c);
                a = ffma2(w.u.x, pv[c].u.x, a);
                a = ffma2(w.u.y, pv[c].u.y, a);
            }
            float v = hsum2(a);
            #pragma unroll
            for (int off = 16; off; off >>= 1) v += __shfl_xor_sync(~0u, v, off);
            s[j] = v;
        }
        if (lane < 8){
            float g = s[0];
            #pragma unroll
            for (int j = 1; j < 8; j++) if (lane == j) g = s[j];
            zr[8*warp + lane] = g + sB[8*warp + lane];
        }
    }

    for (int t = 0; t < TS; ++t){
        // parallel polls: warp0 -> own layer t-1 ; warp1 -> prev layer t+1
        if (t > 0 && tid < NB1){
            const int* p = &g_flag[layer][tid][0];
            while (ld_acq(p) < t) {}
        } else if (t + 1 < TS && tid >= 32 && tid < 32 + nbPrev){
            const int* p = &g_flag[layer-1][tid-32][0];
            while (ld_acq(p) < t + 2) {}
        }
        __syncthreads();

        // issue both gathers up front
        V4 vin[4], pv[4];
        if (t > 0){
            const float* hp = &g_h[layer][t-1][0];
            #pragma unroll
            for (int c = 0; c < 4; c++)
                vin[c].f = __ldcg(reinterpret_cast<const float4*>(hp + 128*c + 4*lane));
        } else {
            #pragma unroll
            for (int c = 0; c < 4; c++) vin[c].f = make_float4(0,0,0,0);
        }
        if (t + 1 < TS){
            const float* hq = &g_h[layer-1][t+1][0];
            #pragma unroll
            for (int c = 0; c < 4; c++)
                pv[c].f = __ldcg(reinterpret_cast<const float4*>(hq + 128*c + 4*lane));
        } else {
            #pragma unroll
            for (int c = 0; c < 4; c++) pv[c].f = make_float4(0,0,0,0);
        }

        // fused compute: phase E (LDS-bound, hides LDG latency) + critical (regs)
        ull accE[8];
        #pragma unroll
        for (int j = 0; j < 8; j++){
            const float* wr = WI + (8*warp + j)*512 + 4*lane;
            ull a = 0ULL;
            #pragma unroll
            for (int c = 0; c < 4; c++){
                V4 w; w.f = *reinterpret_cast<const float4*>(wr + 128*c);
                a = ffma2(w.u.x, pv[c].u.x, a);
                a = ffma2(w.u.y, pv[c].u.y, a);
            }
            accE[j] = a;
        }
        ull acc2[8];
        #pragma unroll
        for (int j = 0; j < 8; j++){
            ull a = 0ULL;
            #pragma unroll
            for (int c = 0; c < 4; c++){
                a = ffma2(wh[j][c].u.x, vin[c].u.x, a);
                a = ffma2(wh[j][c].u.y, vin[c].u.y, a);
            }
            acc2[j] = a;
        }

        // reduce critical -> sG
        {
            float s[8];
            #pragma unroll
            for (int j = 0; j < 8; j++){
                float a = hsum2(acc2[j]);
                #pragma unroll
                for (int off = 16; off; off >>= 1) a += __shfl_xor_sync(~0u, a, off);
                s[j] = a;
            }
            if (lane < 8){
                float g = s[0];
                #pragma unroll
                for (int j = 1; j < 8; j++) if (lane == j) g = s[j];
                sG[8*warp + lane] = g;
            }
        }
        __syncthreads();

        if (tid < 16){
            const float* zz = zr + (t & 1)*64;
            float iv = sigf (sG[tid]      + zz[tid]);
            float fv = sigf (sG[16 + tid] + zz[16 + tid]);
            float gv = tanhf(sG[32 + tid] + zz[32 + tid]);
            float ov = sigf (sG[48 + tid] + zz[48 + tid]);
            cc = fv*cc + iv*gv;
            g_h[layer][t][b*16 + tid] = ov * tanhf(cc);
        }
        if (warp == 0){
            __syncwarp();
            if (lane == 0) st_rel(&g_flag[layer][b][0], t + 1);
        }

        // deferred phase-E reduce -> zr[(t+1)&1]
        if (t + 1 < TS){
            float s[8];
            #pragma unroll
            for (int j = 0; j < 8; j++){
                float a = hsum2(accE[j]);
                #pragma unroll
                for (int off = 16; off; off >>= 1) a += __shfl_xor_sync(~0u, a, off);
                s[j] = a;
            }
            if (lane < 8){
                float g = s[0];
                #pragma unroll
                for (int j = 1; j < 8; j++) if (lane == j) g = s[j];
                zr[((t+1) & 1)*64 + 8*warp + lane] = g + sB[8*warp + lane];
            }
        }
    }
}

__global__ void __launch_bounds__(NT, 1) lstm_kernel(
    const float* __restrict__ x,
    const float* __restrict__ w_ih0, const float* __restrict__ w_hh0,
    const float* __restrict__ b_ih0, const float* __restrict__ b_hh0,
    const float* __restrict__ w_ih,  const float* __restrict__ w_hh,
    const float* __restrict__ b_ih,  const float* __restrict__ b_hh)
{
    extern __shared__ float sm[];
    int bid = blockIdx.x;
    if (bid < NB0){
        run_l0(bid, x, w_ih0, w_hh0, b_ih0, b_hh0, sm);
    } else {
        int r = bid - NB0;
        int layer = 1 + (r >> 5);
        int b = r & 31;
        size_t off = (size_t)(layer - 1) * (4*HD);
        run_l(layer, b, (layer == 1) ? NB0 : NB1,
              w_ih + off*HD, w_hh + off*HD, b_ih + off, b_hh + off, sm);
    }
}

// ---------------- epilogue + helpers ----------------

__global__ void k_zero(){
    int i = blockIdx.x*blockDim.x + threadIdx.x;
    if (i < NL*32*32) (&g_flag[0][0][0])[i] = 0;
}

__global__ void k_dummy(){ if (threadIdx.x == 0) g_dummy = blockIdx.x; }

__global__ void k_e(const float* __restrict__ wlin, const float* __restrict__ blin){
    int t = blockIdx.x;
    int tid = threadIdx.x;
    float a = 0.0f;
    for (int j = tid; j < HD; j += 128) a += g_h[NL-1][t][j] * wlin[j];
    #pragma unroll
    for (int off = 16; off; off >>= 1) a += __shfl_xor_sync(~0u, a, off);
    __shared__ float sr[4];
    if ((tid & 31) == 0) sr[tid >> 5] = a;
    __syncthreads();
    if (tid == 0) g_z[t] = tanhf(sr[0] + sr[1] + sr[2] + sr[3] + blin[0]);
}

__global__ void k_softmax(){
    int tid = threadIdx.x;
    __shared__ float sr[32];
    __shared__ float sbc;
    float z1 = g_z[tid], z2 = g_z[tid + 1024];
    float m = fmaxf(z1, z2);
    #pragma unroll
    for (int off = 16; off; off >>= 1) m = fmaxf(m, __shfl_xor_sync(~0u, m, off));
    if ((tid & 31) == 0) sr[tid >> 5] = m;
    __syncthreads();
    if (tid < 32){
        float v = sr[tid];
        #pragma unroll
        for (int off = 16; off; off >>= 1) v = fmaxf(v, __shfl_xor_sync(~0u, v, off));
        if (tid == 0) sbc = v;
    }
    __syncthreads();
    float mm = sbc;
    float e1 = expf(z1 - mm), e2 = expf(z2 - mm);
    float s = e1 + e2;
    #pragma unroll
    for (int off = 16; off; off >>= 1) s += __shfl_xor_sync(~0u, s, off);
    __syncthreads();
    if ((tid & 31) == 0) sr[tid >> 5] = s;
    __syncthreads();
    if (tid < 32){
        float v = sr[tid];
        #pragma unroll
        for (int off = 16; off; off >>= 1) v += __shfl_xor_sync(~0u, v, off);
        if (tid == 0) sbc = v;
    }
    __syncthreads();
    float inv = 1.0f / (sbc * (float)TS);
    g_wt[tid]        = e1 * inv;
    g_wt[tid + 1024] = e2 * inv;
}

__global__ void k_part(){
    int bb = blockIdx.x, tid = threadIdx.x;
    float a = 0.0f;
    int t0 = bb * 64;
    #pragma unroll 4
    for (int t = t0; t < t0 + 64; ++t) a += g_wt[t] * g_h[NL-1][t][tid];
    g_part[bb][tid] = a;
}

__global__ void k_final(float* __restrict__ out){
    int tid = threadIdx.x;
    float a = 0.0f;
    #pragma unroll
    for (int bb = 0; bb < 32; ++bb) a += g_part[bb][tid];
    out[tid] = a;
}

extern "C" void kernel_launch(void* const* d_in, const int* in_sizes, int n_in,
                              void* d_out, int out_size)
{
    const float* x     = (const float*)d_in[0];
    const float* w_ih0 = (const float*)d_in[1];
    const float* w_hh0 = (const float*)d_in[2];
    const float* b_ih0 = (const float*)d_in[3];
    const float* b_hh0 = (const float*)d_in[4];
    const float* w_ih  = (const float*)d_in[5];
    const float* w_hh  = (const float*)d_in[6];
    const float* b_ih  = (const float*)d_in[7];
    const float* b_hh  = (const float*)d_in[8];
    const float* w_lin = (const float*)d_in[9];
    const float* b_lin = (const float*)d_in[10];

    cudaFuncSetAttribute(lstm_kernel, cudaFuncAttributeMaxDynamicSharedMemorySize, SMEM_BYTES);

    k_zero<<<(NL*32*32 + 255)/256, 256>>>();
    k_dummy<<<1, 32>>>();               // keep lstm_kernel as the 4th launch
    k_dummy<<<1, 32>>>();               // so ncu's capture window hits it
    lstm_kernel<<<TOTAL_BLOCKS, NT, SMEM_BYTES>>>(x, w_ih0, w_hh0, b_ih0, b_hh0,
                                                  w_ih, w_hh, b_ih, b_hh);
    k_e<<<TS, 128>>>(w_lin, b_lin);
    k_softmax<<<1, 1024>>>();
    k_part<<<32, 512>>>();
    k_final<<<1, 512>>>((float*)d_out);
}

// round 13
// speedup vs baseline: 1.0440x; 1.0016x over previous
#include <cuda_runtime.h>
#include <math.h>

// Problem constants
#define TS   2048
#define IIN  64
#define HD   512
#define NL   5

// Partitioning
#define NB0  16      // layer 0: 16 blocks x 128 rows
#define NB1  32      // layers 1..4: 32 blocks x 64 rows
#define NT   256     // 8 warps -> 255-reg budget, weights in RF
#define TOTAL_BLOCKS (NB0 + 4*NB1)   // 144 blocks, 1/SM, co-resident

// Dynamic SMEM (floats):
//  layer0 : 128*256 WS + 128 sG + 128 sB + 256 zx = 33280
//  layer1+: 64*512 WI + 64 sG + 64 sB + 128 zr   = 33024
#define SMEM_BYTES (33280*4)

// Device scratch
__device__ float g_h[NL][TS][HD];
__device__ int   g_flag[NL][32][32];   // one 128B line per (layer, producer)
__device__ float g_z[TS];
__device__ float g_wt[TS];
__device__ float g_part[32][HD];
__device__ int   g_dummy;

typedef unsigned long long ull;

__device__ __forceinline__ float sigf(float v){ return 1.0f/(1.0f + __expf(-v)); }

__device__ __forceinline__ int ld_acq(const int* p){
    int v; asm volatile("ld.global.acquire.gpu.b32 %0, [%1];" : "=r"(v) : "l"(p) : "memory");
    return v;
}
__device__ __forceinline__ void st_rel(int* p, int v){
    asm volatile("st.global.release.gpu.b32 [%0], %1;" :: "l"(p), "r"(v) : "memory");
}
// packed f32x2 FMA (sm_103a FFMA2)
__device__ __forceinline__ ull ffma2(ull a, ull b, ull c){
    ull d; asm("fma.rn.f32x2 %0, %1, %2, %3;" : "=l"(d) : "l"(a), "l"(b), "l"(c));
    return d;
}
__device__ __forceinline__ float hsum2(ull a){
    float x, y; asm("mov.b64 {%0,%1}, %2;" : "=f"(x), "=f"(y) : "l"(a));
    return x + y;
}
__device__ __forceinline__ ull pack2(float x, float y){
    ull r; asm("mov.b64 %0, {%1,%2};" : "=l"(r) : "f"(x), "f"(y));
    return r;
}
union V4 { float4 f; ulonglong2 u; };

// ---------------- layer 0 : 16 blocks x 128 rows, 16 rows/warp ----------------
__device__ void run_l0(int b, const float* __restrict__ x,
                       const float* __restrict__ wih0, const float* __restrict__ whh0,
                       const float* __restrict__ bih0, const float* __restrict__ bhh0,
                       float* sm)
{
    float* WS = sm;               // [128][256] hh cols [0,256)
    float* sG = sm + 128*256;     // [128]
    float* sB = sG + 128;         // [128]
    float* zx = sB + 128;         // [2][128]
    const int tid = threadIdx.x, warp = tid >> 5, lane = tid & 31;

    for (int idx = tid; idx < 128*256; idx += NT){
        int r = idx >> 8, c = idx & 255;
        int grow = (r >> 5)*HD + b*32 + (r & 31);
        WS[idx] = whh0[grow*HD + c];
    }
    V4 wh[16][2]; ull wx[16];
    #pragma unroll
    for (int j = 0; j < 16; j++){
        int r = 16*warp + j;
        int grow = (r >> 5)*HD + b*32 + (r & 31);
        wh[j][0].f = *reinterpret_cast<const float4*>(&whh0[grow*HD + 256 + 4*lane]);
        wh[j][1].f = *reinterpret_cast<const float4*>(&whh0[grow*HD + 384 + 4*lane]);
        float2 t2  = *reinterpret_cast<const float2*>(&wih0[grow*IIN + 2*lane]);
        wx[j] = pack2(t2.x, t2.y);
    }
    if (tid < 128){
        int grow = (tid >> 5)*HD + b*32 + (tid & 31);
        sB[tid] = bih0[grow] + bhh0[grow];
    }
    float cc = 0.0f;
    __syncthreads();

    // prologue: zx[0] = W_ih0 . x_0 + bias
    {
        float2 v2 = *reinterpret_cast<const float2*>(&x[2*lane]);
        ull vx = pack2(v2.x, v2.y);
        float s[16];
        #pragma unroll
        for (int j = 0; j < 16; j++){
            float a = hsum2(ffma2(wx[j], vx, 0ULL));
            #pragma unroll
            for (int off = 16; off; off >>= 1) a += __shfl_xor_sync(~0u, a, off);
            s[j] = a;
        }
        if (lane < 16){
            float g = s[0];
            #pragma unroll
            for (int j = 1; j < 16; j++) if (lane == j) g = s[j];
            zx[16*warp + lane] = g + sB[16*warp + lane];
        }
    }

    for (int t = 0; t < TS; ++t){
        if (t > 0 && tid < NB0){
            const int* p = &g_flag[0][tid][0];
            while (ld_acq(p) < t) {}
        }
        __syncthreads();

        V4 vin[4];
        if (t > 0){
            const float* hp = &g_h[0][t-1][0];
            #pragma unroll
            for (int c = 0; c < 4; c++)
                vin[c].f = __ldcg(reinterpret_cast<const float4*>(hp + 128*c + 4*lane));
        } else {
            #pragma unroll
            for (int c = 0; c < 4; c++) vin[c].f = make_float4(0,0,0,0);
        }

        // critical: SMEM cols [0,256) + reg cols [256,512)
        ull acc2[16];
        #pragma unroll
        for (int j = 0; j < 16; j++){
            const float* wr = WS + (16*warp + j)*256 + 4*lane;
            ull a = 0ULL;
            V4 w0; w0.f = *reinterpret_cast<const float4*>(wr);
            a = ffma2(w0.u.x, vin[0].u.x, a); a = ffma2(w0.u.y, vin[0].u.y, a);
            V4 w1; w1.f = *reinterpret_cast<const float4*>(wr + 128);
            a = ffma2(w1.u.x, vin[1].u.x, a); a = ffma2(w1.u.y, vin[1].u.y, a);
            a = ffma2(wh[j][0].u.x, vin[2].u.x, a); a = ffma2(wh[j][0].u.y, vin[2].u.y, a);
            a = ffma2(wh[j][1].u.x, vin[3].u.x, a); a = ffma2(wh[j][1].u.y, vin[3].u.y, a);
            acc2[j] = a;
        }
        {
            float s[16];
            #pragma unroll
            for (int j = 0; j < 16; j++){
                float a = hsum2(acc2[j]);
                #pragma unroll
                for (int off = 16; off; off >>= 1) a += __shfl_xor_sync(~0u, a, off);
                s[j] = a;
            }
            if (lane < 16){
                float g = s[0];
                #pragma unroll
                for (int j = 1; j < 16; j++) if (lane == j) g = s[j];
                sG[16*warp + lane] = g;
            }
        }
        __syncthreads();

        if (tid < 32){
            const float* zz = zx + (t & 1)*128;
            float iv = sigf (sG[tid]      + zz[tid]);
            float fv = sigf (sG[32 + tid] + zz[32 + tid]);
            float gv = tanhf(sG[64 + tid] + zz[64 + tid]);
            float ov = sigf (sG[96 + tid] + zz[96 + tid]);
            cc = fv*cc + iv*gv;
            g_h[0][t][b*32 + tid] = ov * tanhf(cc);
        }
        if (warp == 0){
            __syncwarp();
            if (lane == 0) st_rel(&g_flag[0][b][0], t + 1);
        }

        // phase E: zx for t+1 (x always available); reuses acc registers
        if (t + 1 < TS){
            float2 v2 = *reinterpret_cast<const float2*>(&x[(t+1)*IIN + 2*lane]);
            ull vx = pack2(v2.x, v2.y);
            float s[16];
            #pragma unroll
            for (int j = 0; j < 16; j++){
                float a = hsum2(ffma2(wx[j], vx, 0ULL));
                #pragma unroll
                for (int off = 16; off; off >>= 1) a += __shfl_xor_sync(~0u, a, off);
                s[j] = a;
            }
            if (lane < 16){
                float g = s[0];
                #pragma unroll
                for (int j = 1; j < 16; j++) if (lane == j) g = s[j];
                zx[((t+1) & 1)*128 + 16*warp + lane] = g + sB[16*warp + lane];
            }
        }
    }
}

// ---------------- layers 1..4 : 32 blocks x 64 rows, 8 rows/warp ----------------
// hh fully in registers (FFMA2); W_ih in SMEM, phase E interleaved with
// the critical phase's LDG latency inside one fused compute section.
__device__ void run_l(int layer, int b, int nbPrev,
                      const float* __restrict__ wih, const float* __restrict__ whh,
                      const float* __restrict__ bih, const float* __restrict__ bhh,
                      float* sm)
{
    float* WI = sm;              // [64][512]
    float* sG = sm + 64*512;     // [64]
    float* sB = sG + 64;         // [64]
    float* zr = sB + 64;         // [2][64]
    const int tid = threadIdx.x, warp = tid >> 5, lane = tid & 31;

    for (int idx = tid; idx < 64*512; idx += NT){
        int r = idx >> 9, c = idx & 511;
        int grow = (r >> 4)*HD + b*16 + (r & 15);
        WI[idx] = wih[grow*HD + c];
    }
    V4 wh[8][4];
    #pragma unroll
    for (int j = 0; j < 8; j++){
        int r = 8*warp + j;
        int grow = (r >> 4)*HD + b*16 + (r & 15);
        #pragma unroll
        for (int c = 0; c < 4; c++)
            wh[j][c].f = *reinterpret_cast<const float4*>(&whh[grow*HD + 128*c + 4*lane]);
    }
    if (tid < 64){
        int grow = (tid >> 4)*HD + b*16 + (tid & 15);
        sB[tid] = bih[grow] + bhh[grow];
    }
    float cc = 0.0f;
    __syncthreads();

    // prologue: zr[0] = W_ih . h^{l-1}_0 + bias
    {
        if (tid < nbPrev){
            const int* p = &g_flag[layer-1][tid][0];
            while (ld_acq(p) < 1) {}
        }
        __syncthreads();
        const float* hp = &g_h[layer-1][0][0];
        V4 pv[4];
        #pragma unroll
        for (int c = 0; c < 4; c++)
            pv[c].f = __ldcg(reinterpret_cast<const float4*>(hp + 128*c + 4*lane));
        float s[8];
        #pragma unroll
        for (int j = 0; j < 8; j++){
            const float* wr = WI + (8*warp + j)*512 + 4*lane;
            ull a = 0ULL;
            #pragma unroll
            for (int c = 0; c < 4; c++){
                V4 w; w.f = *reinterpret_cast<const float4*>(wr + 128*c);
                a = ffma2(w.u.x, pv[c].u.x, a);
                a = ffma2(w.u.y, pv[c].u.y, a);
            }
            float v = hsum2(a);
            #pragma unroll
            for (int off = 16; off; off >>= 1) v += __shfl_xor_sync(~0u, v, off);
            s[j] = v;
        }
        if (lane < 8){
            float g = s[0];
            #pragma unroll
            for (int j = 1; j < 8; j++) if (lane == j) g = s[j];
            zr[8*warp + lane] = g + sB[8*warp + lane];
        }
    }

    for (int t = 0; t < TS; ++t){
        // parallel polls: warp0 -> own layer t-1 ; warp1 -> prev layer t+1
        if (t > 0 && tid < NB1){
            const int* p = &g_flag[layer][tid][0];
            while (ld_acq(p) < t) {}
        } else if (t + 1 < TS && tid >= 32 && tid < 32 + nbPrev){
            const int* p = &g_flag[layer-1][tid-32][0];
            while (ld_acq(p) < t + 2) {}
        }
        __syncthreads();

        // issue both gathers up front
        V4 vin[4], pv[4];
        if (t > 0){
            const float* hp = &g_h[layer][t-1][0];
            #pragma unroll
            for (int c = 0; c < 4; c++)
                vin[c].f = __ldcg(reinterpret_cast<const float4*>(hp + 128*c + 4*lane));
        } else {
            #pragma unroll
            for (int c = 0; c < 4; c++) vin[c].f = make_float4(0,0,0,0);
        }
        if (t + 1 < TS){
            const float* hq = &g_h[layer-1][t+1][0];
            #pragma unroll
            for (int c = 0; c < 4; c++)
                pv[c].f = __ldcg(reinterpret_cast<const float4*>(hq + 128*c + 4*lane));
        } else {
            #pragma unroll
            for (int c = 0; c < 4; c++) pv[c].f = make_float4(0,0,0,0);
        }

        // fused compute: phase E (LDS-bound, hides LDG latency) + critical (regs)
        ull accE[8];
        #pragma unroll
        for (int j = 0; j < 8; j++){
            const float* wr = WI + (8*warp + j)*512 + 4*lane;
            ull a = 0ULL;
            #pragma unroll
            for (int c = 0; c < 4; c++){
                V4 w; w.f = *reinterpret_cast<const float4*>(wr + 128*c);
                a = ffma2(w.u.x, pv[c].u.x, a);
                a = ffma2(w.u.y, pv[c].u.y, a);
            }
            accE[j] = a;
        }
        ull acc2[8];
        #pragma unroll
        for (int j = 0; j < 8; j++){
            ull a = 0ULL;
            #pragma unroll
            for (int c = 0; c < 4; c++){
                a = ffma2(wh[j][c].u.x, vin[c].u.x, a);
                a = ffma2(wh[j][c].u.y, vin[c].u.y, a);
            }
            acc2[j] = a;
        }

        // reduce critical -> sG
        {
            float s[8];
            #pragma unroll
            for (int j = 0; j < 8; j++){
                float a = hsum2(acc2[j]);
                #pragma unroll
                for (int off = 16; off; off >>= 1) a += __shfl_xor_sync(~0u, a, off);
                s[j] = a;
            }
            if (lane < 8){
                float g = s[0];
                #pragma unroll
                for (int j = 1; j < 8; j++) if (lane == j) g = s[j];
                sG[8*warp + lane] = g;
            }
        }
        __syncthreads();

        if (tid < 16){
            const float* zz = zr + (t & 1)*64;
            float iv = sigf (sG[tid]      + zz[tid]);
            float fv = sigf (sG[16 + tid] + zz[16 + tid]);
            float gv = tanhf(sG[32 + tid] + zz[32 + tid]);
            float ov = sigf (sG[48 + tid] + zz[48 + tid]);
            cc = fv*cc + iv*gv;
            g_h[layer][t][b*16 + tid] = ov * tanhf(cc);
        }
        if (warp == 0){
            __syncwarp();
            if (lane == 0) st_rel(&g_flag[layer][b][0], t + 1);
        }

        // deferred phase-E reduce -> zr[(t+1)&1]
        if (t + 1 < TS){
            float s[8];
            #pragma unroll
            for (int j = 0; j < 8; j++){
                float a = hsum2(accE[j]);
                #pragma unroll
                for (int off = 16; off; off >>= 1) a += __shfl_xor_sync(~0u, a, off);
                s[j] = a;
            }
            if (lane < 8){
                float g = s[0];
                #pragma unroll
                for (int j = 1; j < 8; j++) if (lane == j) g = s[j];
                zr[((t+1) & 1)*64 + 8*warp + lane] = g + sB[8*warp + lane];
            }
        }
    }
}

__global__ void __launch_bounds__(NT, 1) lstm_kernel(
    const float* __restrict__ x,
    const float* __restrict__ w_ih0, const float* __restrict__ w_hh0,
    const float* __restrict__ b_ih0, const float* __restrict__ b_hh0,
    const float* __restrict__ w_ih,  const float* __restrict__ w_hh,
    const float* __restrict__ b_ih,  const float* __restrict__ b_hh)
{
    extern __shared__ float sm[];
    int bid = blockIdx.x;
    if (bid < NB0){
        run_l0(bid, x, w_ih0, w_hh0, b_ih0, b_hh0, sm);
    } else {
        int r = bid - NB0;
        int layer = 1 + (r >> 5);
        int b = r & 31;
        size_t off = (size_t)(layer - 1) * (4*HD);
        run_l(layer, b, (layer == 1) ? NB0 : NB1,
              w_ih + off*HD, w_hh + off*HD, b_ih + off, b_hh + off, sm);
    }
}

// ---------------- epilogue + helpers ----------------

__global__ void k_zero(){
    int i = blockIdx.x*blockDim.x + threadIdx.x;
    if (i < NL*32*32) (&g_flag[0][0][0])[i] = 0;
}

__global__ void k_dummy(){ if (threadIdx.x == 0) g_dummy = blockIdx.x; }

__global__ void k_e(const float* __restrict__ wlin, const float* __restrict__ blin){
    int t = blockIdx.x;
    int tid = threadIdx.x;
    float a = 0.0f;
    for (int j = tid; j < HD; j += 128) a += g_h[NL-1][t][j] * wlin[j];
    #pragma unroll
    for (int off = 16; off; off >>= 1) a += __shfl_xor_sync(~0u, a, off);
    __shared__ float sr[4];
    if ((tid & 31) == 0) sr[tid >> 5] = a;
    __syncthreads();
    if (tid == 0) g_z[t] = tanhf(sr[0] + sr[1] + sr[2] + sr[3] + blin[0]);
}

__global__ void k_softmax(){
    int tid = threadIdx.x;
    __shared__ float sr[32];
    __shared__ float sbc;
    float z1 = g_z[tid], z2 = g_z[tid + 1024];
    float m = fmaxf(z1, z2);
    #pragma unroll
    for (int off = 16; off; off >>= 1) m = fmaxf(m, __shfl_xor_sync(~0u, m, off));
    if ((tid & 31) == 0) sr[tid >> 5] = m;
    __syncthreads();
    if (tid < 32){
        float v = sr[tid];
        #pragma unroll
        for (int off = 16; off; off >>= 1) v = fmaxf(v, __shfl_xor_sync(~0u, v, off));
        if (tid == 0) sbc = v;
    }
    __syncthreads();
    float mm = sbc;
    float e1 = expf(z1 - mm), e2 = expf(z2 - mm);
    float s = e1 + e2;
    #pragma unroll
    for (int off = 16; off; off >>= 1) s += __shfl_xor_sync(~0u, s, off);
    __syncthreads();
    if ((tid & 31) == 0) sr[tid >> 5] = s;
    __syncthreads();
    if (tid < 32){
        float v = sr[tid];
        #pragma unroll
        for (int off = 16; off; off >>= 1) v += __shfl_xor_sync(~0u, v, off);
        if (tid == 0) sbc = v;
    }
    __syncthreads();
    float inv = 1.0f / (sbc * (float)TS);
    g_wt[tid]        = e1 * inv;
    g_wt[tid + 1024] = e2 * inv;
}

__global__ void k_part(){
    int bb = blockIdx.x, tid = threadIdx.x;
    float a = 0.0f;
    int t0 = bb * 64;
    #pragma unroll 4
    for (int t = t0; t < t0 + 64; ++t) a += g_wt[t] * g_h[NL-1][t][tid];
    g_part[bb][tid] = a;
}

__global__ void k_final(float* __restrict__ out){
    int tid = threadIdx.x;
    float a = 0.0f;
    #pragma unroll
    for (int bb = 0; bb < 32; ++bb) a += g_part[bb][tid];
    out[tid] = a;
}

extern "C" void kernel_launch(void* const* d_in, const int* in_sizes, int n_in,
                              void* d_out, int out_size)
{
    const float* x     = (const float*)d_in[0];
    const float* w_ih0 = (const float*)d_in[1];
    const float* w_hh0 = (const float*)d_in[2];
    const float* b_ih0 = (const float*)d_in[3];
    const float* b_hh0 = (const float*)d_in[4];
    const float* w_ih  = (const float*)d_in[5];
    const float* w_hh  = (const float*)d_in[6];
    const float* b_ih  = (const float*)d_in[7];
    const float* b_hh  = (const float*)d_in[8];
    const float* w_lin = (const float*)d_in[9];
    const float* b_lin = (const float*)d_in[10];

    cudaFuncSetAttribute(lstm_kernel, cudaFuncAttributeMaxDynamicSharedMemorySize, SMEM_BYTES);

    k_zero<<<(NL*32*32 + 255)/256, 256>>>();
    k_dummy<<<1, 32>>>();               // keep lstm_kernel as the 4th launch
    k_dummy<<<1, 32>>>();               // so ncu's capture window hits it
    lstm_kernel<<<TOTAL_BLOCKS, NT, SMEM_BYTES>>>(x, w_ih0, w_hh0, b_ih0, b_hh0,
                                                  w_ih, w_hh, b_ih, b_hh);
    k_e<<<TS, 128>>>(w_lin, b_lin);
    k_softmax<<<1, 1024>>>();
    k_part<<<32, 512>>>();
    k_final<<<1, 512>>>((float*)d_out);
}

// round 14
// speedup vs baseline: 1.0925x; 1.0464x over previous
#include <cuda_runtime.h>
#include <math.h>

// Problem constants
#define TS   2048
#define IIN  64
#define HD   512
#define NL   5

// Partitioning
#define NB0  16      // layer 0: 16 blocks x 128 rows
#define NB1  32      // layers 1..4: 32 blocks x 64 rows
#define NT   256     // 8 warps -> 255-reg budget, weights in RF
#define TOTAL_BLOCKS (NB0 + 4*NB1)   // 144 blocks, 1/SM, co-resident

// Dynamic SMEM (floats):
//  layer0 : 128*256 WS + 128 sG + 128 sB + 256 zx = 33280
//  layer1+: 64*512 WI + 64 sG + 64 sB + 128 zr   = 33024
#define SMEM_BYTES (33280*4)

// Device scratch
__device__ float g_h[NL][TS][HD];
__device__ int   g_flag[NL][32][32];   // one 128B line per (layer, producer)
__device__ float g_z[TS];
__device__ float g_wt[TS];
__device__ float g_part[32][HD];
__device__ int   g_dummy;

typedef unsigned long long ull;

__device__ __forceinline__ float sigf(float v){ return 1.0f/(1.0f + __expf(-v)); }

__device__ __forceinline__ int ld_acq(const int* p){
    int v; asm volatile("ld.global.acquire.gpu.b32 %0, [%1];" : "=r"(v) : "l"(p) : "memory");
    return v;
}
__device__ __forceinline__ void st_rel(int* p, int v){
    asm volatile("st.global.release.gpu.b32 [%0], %1;" :: "l"(p), "r"(v) : "memory");
}
// packed f32x2 FMA (sm_103a FFMA2)
__device__ __forceinline__ ull ffma2(ull a, ull b, ull c){
    ull d; asm("fma.rn.f32x2 %0, %1, %2, %3;" : "=l"(d) : "l"(a), "l"(b), "l"(c));
    return d;
}
__device__ __forceinline__ float hsum2(ull a){
    float x, y; asm("mov.b64 {%0,%1}, %2;" : "=f"(x), "=f"(y) : "l"(a));
    return x + y;
}
__device__ __forceinline__ ull pack2(float x, float y){
    ull r; asm("mov.b64 %0, {%1,%2};" : "=l"(r) : "f"(x), "f"(y));
    return r;
}
union V4 { float4 f; ulonglong2 u; };

// ---------------- layer 0 : 16 blocks x 128 rows, 16 rows/warp ----------------
__device__ void run_l0(int b, const float* __restrict__ x,
                       const float* __restrict__ wih0, const float* __restrict__ whh0,
                       const float* __restrict__ bih0, const float* __restrict__ bhh0,
                       float* sm)
{
    float* WS = sm;               // [128][256] hh cols [0,256)
    float* sG = sm + 128*256;     // [128]
    float* sB = sG + 128;         // [128]
    float* zx = sB + 128;         // [2][128]
    const int tid = threadIdx.x, warp = tid >> 5, lane = tid & 31;

    for (int idx = tid; idx < 128*256; idx += NT){
        int r = idx >> 8, c = idx & 255;
        int grow = (r >> 5)*HD + b*32 + (r & 31);
        WS[idx] = whh0[grow*HD + c];
    }
    V4 wh[16][2]; ull wx[16];
    #pragma unroll
    for (int j = 0; j < 16; j++){
        int r = 16*warp + j;
        int grow = (r >> 5)*HD + b*32 + (r & 31);
        wh[j][0].f = *reinterpret_cast<const float4*>(&whh0[grow*HD + 256 + 4*lane]);
        wh[j][1].f = *reinterpret_cast<const float4*>(&whh0[grow*HD + 384 + 4*lane]);
        float2 t2  = *reinterpret_cast<const float2*>(&wih0[grow*IIN + 2*lane]);
        wx[j] = pack2(t2.x, t2.y);
    }
    if (tid < 128){
        int grow = (tid >> 5)*HD + b*32 + (tid & 31);
        sB[tid] = bih0[grow] + bhh0[grow];
    }
    float cc = 0.0f;
    __syncthreads();

    // prologue: zx[0] = W_ih0 . x_0 + bias
    {
        float2 v2 = *reinterpret_cast<const float2*>(&x[2*lane]);
        ull vx = pack2(v2.x, v2.y);
        float s[16];
        #pragma unroll
        for (int j = 0; j < 16; j++){
            float a = hsum2(ffma2(wx[j], vx, 0ULL));
            #pragma unroll
            for (int off = 16; off; off >>= 1) a += __shfl_xor_sync(~0u, a, off);
            s[j] = a;
        }
        if (lane < 16){
            float g = s[0];
            #pragma unroll
            for (int j = 1; j < 16; j++) if (lane == j) g = s[j];
            zx[16*warp + lane] = g + sB[16*warp + lane];
        }
    }

    for (int t = 0; t < TS; ++t){
        if (t > 0 && tid < NB0){
            const int* p = &g_flag[0][tid][0];
            while (ld_acq(p) < t) {}
        }
        __syncthreads();

        V4 vin[4];
        if (t > 0){
            const float* hp = &g_h[0][t-1][0];
            #pragma unroll
            for (int c = 0; c < 4; c++)
                vin[c].f = __ldcg(reinterpret_cast<const float4*>(hp + 128*c + 4*lane));
        } else {
            #pragma unroll
            for (int c = 0; c < 4; c++) vin[c].f = make_float4(0,0,0,0);
        }

        // critical: SMEM cols [0,256) + reg cols [256,512)
        ull acc2[16];
        #pragma unroll
        for (int j = 0; j < 16; j++){
            const float* wr = WS + (16*warp + j)*256 + 4*lane;
            ull a = 0ULL;
            V4 w0; w0.f = *reinterpret_cast<const float4*>(wr);
            a = ffma2(w0.u.x, vin[0].u.x, a); a = ffma2(w0.u.y, vin[0].u.y, a);
            V4 w1; w1.f = *reinterpret_cast<const float4*>(wr + 128);
            a = ffma2(w1.u.x, vin[1].u.x, a); a = ffma2(w1.u.y, vin[1].u.y, a);
            a = ffma2(wh[j][0].u.x, vin[2].u.x, a); a = ffma2(wh[j][0].u.y, vin[2].u.y, a);
            a = ffma2(wh[j][1].u.x, vin[3].u.x, a); a = ffma2(wh[j][1].u.y, vin[3].u.y, a);
            acc2[j] = a;
        }
        {
            float s[16];
            #pragma unroll
            for (int j = 0; j < 16; j++){
                float a = hsum2(acc2[j]);
                #pragma unroll
                for (int off = 16; off; off >>= 1) a += __shfl_xor_sync(~0u, a, off);
                s[j] = a;
            }
            if (lane < 16){
                float g = s[0];
                #pragma unroll
                for (int j = 1; j < 16; j++) if (lane == j) g = s[j];
                sG[16*warp + lane] = g;
            }
        }
        __syncthreads();

        if (tid < 32){
            const float* zz = zx + (t & 1)*128;
            float iv = sigf (sG[tid]      + zz[tid]);
            float fv = sigf (sG[32 + tid] + zz[32 + tid]);
            float gv = tanhf(sG[64 + tid] + zz[64 + tid]);
            float ov = sigf (sG[96 + tid] + zz[96 + tid]);
            cc = fv*cc + iv*gv;
            g_h[0][t][b*32 + tid] = ov * tanhf(cc);
        }
        if (warp == 0){
            __syncwarp();
            if (lane == 0) st_rel(&g_flag[0][b][0], t + 1);
        }

        // phase E: zx for t+1 (x always available); reuses acc registers
        if (t + 1 < TS){
            float2 v2 = *reinterpret_cast<const float2*>(&x[(t+1)*IIN + 2*lane]);
            ull vx = pack2(v2.x, v2.y);
            float s[16];
            #pragma unroll
            for (int j = 0; j < 16; j++){
                float a = hsum2(ffma2(wx[j], vx, 0ULL));
                #pragma unroll
                for (int off = 16; off; off >>= 1) a += __shfl_xor_sync(~0u, a, off);
                s[j] = a;
            }
            if (lane < 16){
                float g = s[0];
                #pragma unroll
                for (int j = 1; j < 16; j++) if (lane == j) g = s[j];
                zx[((t+1) & 1)*128 + 16*warp + lane] = g + sB[16*warp + lane];
            }
        }
    }
}

// ---------------- layers 1..4 : 32 blocks x 64 rows, 8 rows/warp ----------------
// hh fully in registers (FFMA2); W_ih in SMEM, phase E interleaved with
// the critical phase's LDG latency inside one fused compute section.
__device__ void run_l(int layer, int b, int nbPrev,
                      const float* __restrict__ wih, const float* __restrict__ whh,
                      const float* __restrict__ bih, const float* __restrict__ bhh,
                      float* sm)
{
    float* WI = sm;              // [64][512]
    float* sG = sm + 64*512;     // [64]
    float* sB = sG + 64;         // [64]
    float* zr = sB + 64;         // [2][64]
    const int tid = threadIdx.x, warp = tid >> 5, lane = tid & 31;

    for (int idx = tid; idx < 64*512; idx += NT){
        int r = idx >> 9, c = idx & 511;
        int grow = (r >> 4)*HD + b*16 + (r & 15);
        WI[idx] = wih[grow*HD + c];
    }
    V4 wh[8][4];
    #pragma unroll
    for (int j = 0; j < 8; j++){
        int r = 8*warp + j;
        int grow = (r >> 4)*HD + b*16 + (r & 15);
        #pragma unroll
        for (int c = 0; c < 4; c++)
            wh[j][c].f = *reinterpret_cast<const float4*>(&whh[grow*HD + 128*c + 4*lane]);
    }
    if (tid < 64){
        int grow = (tid >> 4)*HD + b*16 + (tid & 15);
        sB[tid] = bih[grow] + bhh[grow];
    }
    float cc = 0.0f;
    __syncthreads();

    // prologue: zr[0] = W_ih . h^{l-1}_0 + bias
    {
        if (tid < nbPrev){
            const int* p = &g_flag[layer-1][tid][0];
            while (ld_acq(p) < 1) {}
        }
        __syncthreads();
        const float* hp = &g_h[layer-1][0][0];
        V4 pv[4];
        #pragma unroll
        for (int c = 0; c < 4; c++)
            pv[c].f = __ldcg(reinterpret_cast<const float4*>(hp + 128*c + 4*lane));
        float s[8];
        #pragma unroll
        for (int j = 0; j < 8; j++){
            const float* wr = WI + (8*warp + j)*512 + 4*lane;
            ull a = 0ULL;
            #pragma unroll
            for (int c = 0; c < 4; c++){
                V4 w; w.f = *reinterpret_cast<const float4*>(wr + 128*c);
                a = ffma2(w.u.x, pv[c].u.x, a);
                a = ffma2(w.u.y, pv[c].u.y, a);
            }
            float v = hsum2(a);
            #pragma unroll
            for (int off = 16; off; off >>= 1) v += __shfl_xor_sync(~0u, v, off);
            s[j] = v;
        }
        if (lane < 8){
            float g = s[0];
            #pragma unroll
            for (int j = 1; j < 8; j++) if (lane == j) g = s[j];
            zr[8*warp + lane] = g + sB[8*warp + lane];
        }
    }

    for (int t = 0; t < TS; ++t){
        // parallel polls: warp0 -> own layer t-1 ; warp1 -> prev layer t+1
        if (t > 0 && tid < NB1){
            const int* p = &g_flag[layer][tid][0];
            while (ld_acq(p) < t) {}
        } else if (t + 1 < TS && tid >= 32 && tid < 32 + nbPrev){
            const int* p = &g_flag[layer-1][tid-32][0];
            while (ld_acq(p) < t + 2) {}
        }
        __syncthreads();

        // issue both gathers up front
        V4 vin[4], pv[4];
        if (t > 0){
            const float* hp = &g_h[layer][t-1][0];
            #pragma unroll
            for (int c = 0; c < 4; c++)
                vin[c].f = __ldcg(reinterpret_cast<const float4*>(hp + 128*c + 4*lane));
        } else {
            #pragma unroll
            for (int c = 0; c < 4; c++) vin[c].f = make_float4(0,0,0,0);
        }
        if (t + 1 < TS){
            const float* hq = &g_h[layer-1][t+1][0];
            #pragma unroll
            for (int c = 0; c < 4; c++)
                pv[c].f = __ldcg(reinterpret_cast<const float4*>(hq + 128*c + 4*lane));
        } else {
            #pragma unroll
            for (int c = 0; c < 4; c++) pv[c].f = make_float4(0,0,0,0);
        }

        // fused compute: phase E (LDS-bound, hides LDG latency) + critical (regs)
        ull accE[8];
        #pragma unroll
        for (int j = 0; j < 8; j++){
            const float* wr = WI + (8*warp + j)*512 + 4*lane;
            ull a = 0ULL;
            #pragma unroll
            for (int c = 0; c < 4; c++){
                V4 w; w.f = *reinterpret_cast<const float4*>(wr + 128*c);
                a = ffma2(w.u.x, pv[c].u.x, a);
                a = ffma2(w.u.y, pv[c].u.y, a);
            }
            accE[j] = a;
        }
        ull acc2[8];
        #pragma unroll
        for (int j = 0; j < 8; j++){
            ull a = 0ULL;
            #pragma unroll
            for (int c = 0; c < 4; c++){
                a = ffma2(wh[j][c].u.x, vin[c].u.x, a);
                a = ffma2(wh[j][c].u.y, vin[c].u.y, a);
            }
            acc2[j] = a;
        }

        // reduce critical -> sG
        {
            float s[8];
            #pragma unroll
            for (int j = 0; j < 8; j++){
                float a = hsum2(acc2[j]);
                #pragma unroll
                for (int off = 16; off; off >>= 1) a += __shfl_xor_sync(~0u, a, off);
                s[j] = a;
            }
            if (lane < 8){
                float g = s[0];
                #pragma unroll
                for (int j = 1; j < 8; j++) if (lane == j) g = s[j];
                sG[8*warp + lane] = g;
            }
        }
        __syncthreads();

        if (tid < 16){
            const float* zz = zr + (t & 1)*64;
            float iv = sigf (sG[tid]      + zz[tid]);
            float fv = sigf (sG[16 + tid] + zz[16 + tid]);
            float gv = tanhf(sG[32 + tid] + zz[32 + tid]);
            float ov = sigf (sG[48 + tid] + zz[48 + tid]);
            cc = fv*cc + iv*gv;
            g_h[layer][t][b*16 + tid] = ov * tanhf(cc);
        }
        if (warp == 0){
            __syncwarp();
            if (lane == 0) st_rel(&g_flag[layer][b][0], t + 1);
        }

        // deferred phase-E reduce -> zr[(t+1)&1]
        if (t + 1 < TS){
            float s[8];
            #pragma unroll
            for (int j = 0; j < 8; j++){
                float a = hsum2(accE[j]);
                #pragma unroll
                for (int off = 16; off; off >>= 1) a += __shfl_xor_sync(~0u, a, off);
                s[j] = a;
            }
            if (lane < 8){
                float g = s[0];
                #pragma unroll
                for (int j = 1; j < 8; j++) if (lane == j) g = s[j];
                zr[((t+1) & 1)*64 + 8*warp + lane] = g + sB[8*warp + lane];
            }
        }
    }
}

__global__ void __launch_bounds__(NT, 1) lstm_kernel(
    const float* __restrict__ x,
    const float* __restrict__ w_ih0, const float* __restrict__ w_hh0,
    const float* __restrict__ b_ih0, const float* __restrict__ b_hh0,
    const float* __restrict__ w_ih,  const float* __restrict__ w_hh,
    const float* __restrict__ b_ih,  const float* __restrict__ b_hh)
{
    extern __shared__ float sm[];
    int bid = blockIdx.x;
    if (bid < NB0){
        run_l0(bid, x, w_ih0, w_hh0, b_ih0, b_hh0, sm);
    } else {
        int r = bid - NB0;
        int layer = 1 + (r >> 5);
        int b = r & 31;
        size_t off = (size_t)(layer - 1) * (4*HD);
        run_l(layer, b, (layer == 1) ? NB0 : NB1,
              w_ih + off*HD, w_hh + off*HD, b_ih + off, b_hh + off, sm);
    }
}

// ---------------- epilogue + helpers ----------------

__global__ void k_zero(){
    int i = blockIdx.x*blockDim.x + threadIdx.x;
    if (i < NL*32*32) (&g_flag[0][0][0])[i] = 0;
}

__global__ void k_dummy(){ if (threadIdx.x == 0) g_dummy = blockIdx.x; }

__global__ void k_e(const float* __restrict__ wlin, const float* __restrict__ blin){
    int t = blockIdx.x;
    int tid = threadIdx.x;
    float a = 0.0f;
    for (int j = tid; j < HD; j += 128) a += g_h[NL-1][t][j] * wlin[j];
    #pragma unroll
    for (int off = 16; off; off >>= 1) a += __shfl_xor_sync(~0u, a, off);
    __shared__ float sr[4];
    if ((tid & 31) == 0) sr[tid >> 5] = a;
    __syncthreads();
    if (tid == 0) g_z[t] = tanhf(sr[0] + sr[1] + sr[2] + sr[3] + blin[0]);
}

__global__ void k_softmax(){
    int tid = threadIdx.x;
    __shared__ float sr[32];
    __shared__ float sbc;
    float z1 = g_z[tid], z2 = g_z[tid + 1024];
    float m = fmaxf(z1, z2);
    #pragma unroll
    for (int off = 16; off; off >>= 1) m = fmaxf(m, __shfl_xor_sync(~0u, m, off));
    if ((tid & 31) == 0) sr[tid >> 5] = m;
    __syncthreads();
    if (tid < 32){
        float v = sr[tid];
        #pragma unroll
        for (int off = 16; off; off >>= 1) v = fmaxf(v, __shfl_xor_sync(~0u, v, off));
        if (tid == 0) sbc = v;
    }
    __syncthreads();
    float mm = sbc;
    float e1 = expf(z1 - mm), e2 = expf(z2 - mm);
    float s = e1 + e2;
    #pragma unroll
    for (int off = 16; off; off >>= 1) s += __shfl_xor_sync(~0u, s, off);
    __syncthreads();
    if ((tid & 31) == 0) sr[tid >> 5] = s;
    __syncthreads();
    if (tid < 32){
        float v = sr[tid];
        #pragma unroll
        for (int off = 16; off; off >>= 1) v += __shfl_xor_sync(~0u, v, off);
        if (tid == 0) sbc = v;
    }
    __syncthreads();
    float inv = 1.0f / (sbc * (float)TS);
    g_wt[tid]        = e1 * inv;
    g_wt[tid + 1024] = e2 * inv;
}

__global__ void k_part(){
    int bb = blockIdx.x, tid = threadIdx.x;
    float a = 0.0f;
    int t0 = bb * 64;
    #pragma unroll 4
    for (int t = t0; t < t0 + 64; ++t) a += g_wt[t] * g_h[NL-1][t][tid];
    g_part[bb][tid] = a;
}

__global__ void k_final(float* __restrict__ out){
    int tid = threadIdx.x;
    float a = 0.0f;
    #pragma unroll
    for (int bb = 0; bb < 32; ++bb) a += g_part[bb][tid];
    out[tid] = a;
}

extern "C" void kernel_launch(void* const* d_in, const int* in_sizes, int n_in,
                              void* d_out, int out_size)
{
    const float* x     = (const float*)d_in[0];
    const float* w_ih0 = (const float*)d_in[1];
    const float* w_hh0 = (const float*)d_in[2];
    const float* b_ih0 = (const float*)d_in[3];
    const float* b_hh0 = (const float*)d_in[4];
    const float* w_ih  = (const float*)d_in[5];
    const float* w_hh  = (const float*)d_in[6];
    const float* b_ih  = (const float*)d_in[7];
    const float* b_hh  = (const float*)d_in[8];
    const float* w_lin = (const float*)d_in[9];
    const float* b_lin = (const float*)d_in[10];

    cudaFuncSetAttribute(lstm_kernel, cudaFuncAttributeMaxDynamicSharedMemorySize, SMEM_BYTES);

    k_zero<<<(NL*32*32 + 255)/256, 256>>>();
    k_dummy<<<1, 32>>>();               // keep lstm_kernel as the 4th launch
    k_dummy<<<1, 32>>>();               // so ncu's capture window hits it
    lstm_kernel<<<TOTAL_BLOCKS, NT, SMEM_BYTES>>>(x, w_ih0, w_hh0, b_ih0, b_hh0,
                                                  w_ih, w_hh, b_ih, b_hh);
    k_e<<<TS, 128>>>(w_lin, b_lin);
    k_softmax<<<1, 1024>>>();
    k_part<<<32, 512>>>();
    k_final<<<1, 512>>>((float*)d_out);
}